// round 2
// baseline (speedup 1.0000x reference)
#include <cuda_runtime.h>

#define TT    16
#define BB    32
#define IDIM  512
#define HDIM  1024
#define DECAYF 0.999f
#define KSPLIT 8

// ---------------- scratch (device globals; no allocations) ----------------
__device__ float g_R[TT*BB*IDIM];      // right_s = x_s @ inpt_mat   [s][b][i]
__device__ float g_D[TT*TT*BB];        // D[t][s][b] = x_t[b] . R_s[b]
__device__ float g_ybase[TT*BB*HDIM];  // x_t @ main_mat^T + bias
__device__ float g_y[BB*HDIM];         // current corrected y (input to W1 gemm)
__device__ float g_h[BB*HDIM];         // relu hidden
__device__ float g_L[TT*BB*HDIM];      // left_s = yp_s @ hid_mat^T
__device__ float g_part[KSPLIT*BB*HDIM];
__device__ unsigned int g_sem[16];     // zero-init; reset by reducer each use

#define FMA16() \
    acc[0][0] += a.x*b.x; acc[0][1] += a.x*b.y; acc[0][2] += a.x*b.z; acc[0][3] += a.x*b.w; \
    acc[1][0] += a.y*b.x; acc[1][1] += a.y*b.y; acc[1][2] += a.y*b.z; acc[1][3] += a.y*b.w; \
    acc[2][0] += a.z*b.x; acc[2][1] += a.z*b.y; acc[2][2] += a.z*b.z; acc[2][3] += a.z*b.w; \
    acc[3][0] += a.w*b.x; acc[3][1] += a.w*b.y; acc[3][2] += a.w*b.z; acc[3][3] += a.w*b.w;

// ---------------------------------------------------------------------------
// kR: R = X @ inpt_mat   (NN gemm, M=512 (=T*B), N=512, K=512)
// grid (16 mtiles of 32, 8 ntiles of 64), 128 threads, 4x4 micro-tile
// ---------------------------------------------------------------------------
__global__ void kR(const float* __restrict__ X, const float* __restrict__ Bm)
{
    const int K = IDIM, N = IDIM;
    int mtile = blockIdx.x, ntile = blockIdx.y;
    int tid = threadIdx.x;
    __shared__ __align__(16) float As[32*36];   // [k][m], padded stride 36
    __shared__ __align__(16) float Bs[32*68];   // [k][n], padded stride 68
    float acc[4][4] = {};
    int tx = tid & 15, ty = tid >> 4;
    int m0 = ty*4, n0 = tx*4;
    for (int kb = 0; kb < K; kb += 32) {
        int k4 = tid & 7;
        int mrow = tid >> 3;               // 0..15
        #pragma unroll
        for (int r = 0; r < 2; r++) {
            int mm = mrow + r*16;
            float4 v = *(const float4*)(X + (mtile*32+mm)*K + kb + k4*4);
            As[(k4*4+0)*36+mm] = v.x;
            As[(k4*4+1)*36+mm] = v.y;
            As[(k4*4+2)*36+mm] = v.z;
            As[(k4*4+3)*36+mm] = v.w;
        }
        int n4 = tid & 15, kq = tid >> 4;  // kq 0..7
        #pragma unroll
        for (int r = 0; r < 4; r++) {
            int k = kq + r*8;
            float4 v = *(const float4*)(Bm + (kb+k)*N + ntile*64 + n4*4);
            *(float4*)&Bs[k*68 + n4*4] = v;
        }
        __syncthreads();
        #pragma unroll
        for (int kk = 0; kk < 32; kk++) {
            float4 a = *(const float4*)(As + kk*36 + m0);
            float4 b = *(const float4*)(Bs + kk*68 + n0);
            FMA16()
        }
        __syncthreads();
    }
    #pragma unroll
    for (int i = 0; i < 4; i++)
        *(float4*)&g_R[(mtile*32+m0+i)*N + ntile*64 + n0] =
            make_float4(acc[i][0], acc[i][1], acc[i][2], acc[i][3]);
}

// ---------------------------------------------------------------------------
// kYbase: ybase = X @ main_mat^T + bias  (NT gemm, M=512, N=1024, K=512)
// Also seeds g_y with the t=0 rows. grid (16 ntiles, 8 mtiles), 256 threads.
// ---------------------------------------------------------------------------
__global__ void kYbase(const float* __restrict__ X, const float* __restrict__ W,
                       const float* __restrict__ bias)
{
    const int K = IDIM, N = HDIM;
    int ntile = blockIdx.x, mtile = blockIdx.y;
    int tid = threadIdx.x;
    __shared__ __align__(16) float As[32*68];   // [k][m] (64 m)
    __shared__ __align__(16) float Bs[32*68];   // [k][n] (64 n)
    float acc[4][4] = {};
    int tx = tid & 15, ty = tid >> 4;           // ty 0..15
    int m0 = ty*4, n0 = tx*4;
    for (int kb = 0; kb < K; kb += 32) {
        int k4 = tid & 7;
        int row = tid >> 3;                     // 0..31
        #pragma unroll
        for (int r = 0; r < 2; r++) {
            int mm = row + r*32;
            float4 v = *(const float4*)(X + (mtile*64+mm)*K + kb + k4*4);
            As[(k4*4+0)*68+mm] = v.x;
            As[(k4*4+1)*68+mm] = v.y;
            As[(k4*4+2)*68+mm] = v.z;
            As[(k4*4+3)*68+mm] = v.w;
        }
        #pragma unroll
        for (int r = 0; r < 2; r++) {
            int nn = row + r*32;
            float4 v = *(const float4*)(W + (ntile*64+nn)*K + kb + k4*4);
            Bs[(k4*4+0)*68+nn] = v.x;
            Bs[(k4*4+1)*68+nn] = v.y;
            Bs[(k4*4+2)*68+nn] = v.z;
            Bs[(k4*4+3)*68+nn] = v.w;
        }
        __syncthreads();
        #pragma unroll
        for (int kk = 0; kk < 32; kk++) {
            float4 a = *(const float4*)(As + kk*68 + m0);
            float4 b = *(const float4*)(Bs + kk*68 + n0);
            FMA16()
        }
        __syncthreads();
    }
    #pragma unroll
    for (int i = 0; i < 4; i++) {
        int grow = mtile*64 + m0 + i;
        int col0 = ntile*64 + n0;
        float4 v = make_float4(acc[i][0] + bias[col0+0],
                               acc[i][1] + bias[col0+1],
                               acc[i][2] + bias[col0+2],
                               acc[i][3] + bias[col0+3]);
        *(float4*)&g_ybase[grow*N + col0] = v;
        if (grow < BB) *(float4*)&g_y[grow*N + col0] = v;   // t=0 init
    }
}

// ---------------------------------------------------------------------------
// kD: D[t][s][b] = x_t[b] . R_s[b]  for s < t
// ---------------------------------------------------------------------------
__global__ void kD(const float* __restrict__ X)
{
    int t = blockIdx.x, s = blockIdx.y;
    if (s >= t) return;
    int w = threadIdx.x >> 5, lane = threadIdx.x & 31;
    for (int b = w; b < BB; b += 8) {
        const float* xb = X + (t*BB + b)*IDIM;
        const float* rb = g_R + (s*BB + b)*IDIM;
        float sum = 0.f;
        for (int i = lane; i < IDIM; i += 32) sum += xb[i]*rb[i];
        #pragma unroll
        for (int o = 16; o > 0; o >>= 1) sum += __shfl_down_sync(0xffffffffu, sum, o);
        if (lane == 0) g_D[(t*TT + s)*BB + b] = sum;
    }
}

// ---------------------------------------------------------------------------
// gemm32: C[32,1024] = A[32,1024] @ W[1024,1024]^T  (+bias, +relu, +epilogue)
// Split-K (8 ways) with deterministic semaphore fan-in reduction.
// MODE 1: A=g_y,  out = relu(.+b1) -> g_h
// MODE 2: A=g_h,  out = .+b2      -> Cout (yp for step t)
// MODE 3: A=yp,   out             -> g_L[t];  epilogue computes y_{t+1}
// grid (16 ntiles, 8 ksplits), 128 threads, 4x4 micro-tile
// ---------------------------------------------------------------------------
template<int MODE>
__global__ void gemm32_k(const float* __restrict__ Aext, const float* __restrict__ W,
                         const float* __restrict__ bias, float* __restrict__ Cout, int t)
{
    const int K = HDIM, N = HDIM;
    int bx = blockIdx.x;   // ntile
    int ks = blockIdx.y;   // ksplit
    int tid = threadIdx.x;
    const float* A = (MODE==1) ? g_y : (MODE==2) ? g_h : Aext;
    __shared__ __align__(16) float As[32*36];
    __shared__ __align__(16) float Bs[32*68];
    float acc[4][4] = {};
    int tx = tid & 15, ty = tid >> 4;   // ty 0..7
    int m0 = ty*4, n0 = tx*4;
    int kstart = ks*(K/KSPLIT);
    for (int kb = kstart; kb < kstart + K/KSPLIT; kb += 32) {
        int k4 = tid & 7;
        int mrow = tid >> 3;            // 0..15
        #pragma unroll
        for (int r = 0; r < 2; r++) {
            int mm = mrow + r*16;
            float4 v = *(const float4*)(A + mm*K + kb + k4*4);
            As[(k4*4+0)*36+mm] = v.x;
            As[(k4*4+1)*36+mm] = v.y;
            As[(k4*4+2)*36+mm] = v.z;
            As[(k4*4+3)*36+mm] = v.w;
        }
        #pragma unroll
        for (int r = 0; r < 4; r++) {
            int nn = mrow + r*16;
            float4 v = *(const float4*)(W + (bx*64+nn)*K + kb + k4*4);
            Bs[(k4*4+0)*68+nn] = v.x;
            Bs[(k4*4+1)*68+nn] = v.y;
            Bs[(k4*4+2)*68+nn] = v.z;
            Bs[(k4*4+3)*68+nn] = v.w;
        }
        __syncthreads();
        #pragma unroll
        for (int kk = 0; kk < 32; kk++) {
            float4 a = *(const float4*)(As + kk*36 + m0);
            float4 b = *(const float4*)(Bs + kk*68 + n0);
            FMA16()
        }
        __syncthreads();
    }
    // store partial tile
    #pragma unroll
    for (int i = 0; i < 4; i++)
        *(float4*)&g_part[(ks*32 + m0 + i)*N + bx*64 + n0] =
            make_float4(acc[i][0], acc[i][1], acc[i][2], acc[i][3]);
    __threadfence();
    __syncthreads();
    __shared__ unsigned last;
    if (tid == 0) {
        unsigned old = atomicAdd(&g_sem[bx], 1u);
        last = (old == KSPLIT-1) ? 1u : 0u;
        if (last) atomicExch(&g_sem[bx], 0u);   // re-arm for next gemm launch
    }
    __syncthreads();
    if (!last) return;
    __threadfence();
    // deterministic fan-in reduction + epilogue (2048 elems / 128 threads)
    for (int e = tid; e < 32*64; e += 128) {
        int m = e >> 6, n = e & 63;
        int col = bx*64 + n;
        float s = 0.f;
        #pragma unroll
        for (int kq = 0; kq < KSPLIT; kq++) s += g_part[(kq*32 + m)*N + col];
        if (MODE == 1) {
            s += bias[col];
            g_h[m*N + col] = fmaxf(s, 0.f);
        } else if (MODE == 2) {
            Cout[m*N + col] = s + bias[col];
        } else {
            g_L[(t*BB + m)*N + col] = s;
            if (t < TT-1) {
                // y_{t+1}[m,col] = ybase + sum_{s2<=t} d^{t-s2} D[t+1][s2][m] * L[s2][m,col]
                float accy = g_ybase[((t+1)*BB + m)*N + col];
                float dp = 1.f;
                for (int s2 = t; s2 >= 0; s2--) {
                    float lv = (s2 == t) ? s : g_L[(s2*BB + m)*N + col];
                    accy += dp * g_D[((t+1)*TT + s2)*BB + m] * lv;
                    dp *= DECAYF;
                }
                g_y[m*N + col] = accy;
            }
        }
    }
}

// ---------------------------------------------------------------------------
extern "C" void kernel_launch(void* const* d_in, const int* in_sizes, int n_in,
                              void* d_out, int out_size)
{
    (void)in_sizes; (void)n_in; (void)out_size;
    const float* x     = (const float*)d_in[0];
    const float* inpt  = (const float*)d_in[1];
    const float* hid   = (const float*)d_in[2];
    const float* mainW = (const float*)d_in[3];
    const float* mainb = (const float*)d_in[4];
    const float* W1    = (const float*)d_in[5];
    const float* b1    = (const float*)d_in[6];
    const float* W2    = (const float*)d_in[7];
    const float* b2    = (const float*)d_in[8];
    float* out = (float*)d_out;

    // recurrence-independent precompute
    kR     <<<dim3(16, 8),  128>>>(x, inpt);
    kYbase <<<dim3(16, 8),  256>>>(x, mainW, mainb);
    kD     <<<dim3(16, 16), 256>>>(x);

    // sequential recurrence: 3 launches per step
    for (int t = 0; t < TT; t++) {
        float* yp = out + t*BB*HDIM;
        gemm32_k<1><<<dim3(16, 8), 128>>>(nullptr, W1,  b1,      nullptr, t);
        gemm32_k<2><<<dim3(16, 8), 128>>>(nullptr, W2,  b2,      yp,      t);
        gemm32_k<3><<<dim3(16, 8), 128>>>(yp,      hid, nullptr, nullptr, t);
    }
}

// round 3
// speedup vs baseline: 2.0203x; 2.0203x over previous
#include <cuda_runtime.h>

#define TT     16
#define BB     32
#define IDIM   512
#define HDIM   1024
#define DECAYF 0.999f

#define NBLK   128      // persistent blocks (all resident on 148 SMs)
#define NTHR   256
#define KS     32       // k-splits (k-slice = 32)
#define NTILES 4        // n-tiles of width 256

// ---------------- scratch (device globals; no allocations) ----------------
__device__ float g_R[TT*BB*IDIM];      // right_s = x_s @ inpt_mat
__device__ float g_D[TT*TT*BB];        // D[t][s][b] = x_t[b] . R_s[b]
__device__ float g_ybase[TT*BB*HDIM];  // x_t @ main_mat^T + bias
__device__ float g_L[TT*BB*HDIM];      // left_s = yp_s @ hid_mat^T
__device__ float g_A[BB*HDIM];         // current GEMM A operand
__device__ float g_part[2][KS*BB*HDIM];// ping-pong K-split partials (8 MB)
__device__ unsigned g_cnt;
__device__ volatile unsigned g_gen;

// ---------------- packed fp32x2 helpers (Blackwell FFMA2) ------------------
__device__ __forceinline__ void ffma2(unsigned long long &d, unsigned long long a,
                                      unsigned long long b)
{
    asm("fma.rn.f32x2 %0, %1, %2, %0;" : "+l"(d) : "l"(a), "l"(b));
}
__device__ __forceinline__ unsigned long long rep2(float x)
{
    unsigned long long r;
    asm("mov.b64 %0, {%1, %1};" : "=l"(r) : "f"(x));
    return r;
}

// ---------------- software grid barrier ------------------------------------
__device__ __forceinline__ void gridbar()
{
    __syncthreads();
    if (threadIdx.x == 0) {
        unsigned gen = g_gen;
        __threadfence();                       // publish this block's writes
        unsigned old = atomicAdd(&g_cnt, 1u);
        if (old == NBLK - 1u) {
            g_cnt = 0u;
            __threadfence();
            g_gen = gen + 1u;                  // release
            __threadfence();                   // invalidate own L1 (CCTL.IVALL)
        } else {
            while (g_gen == gen) { }           // volatile spin
            __threadfence();                   // acquire: invalidate L1
        }
    }
    __syncthreads();
}

// ---------------------------------------------------------------------------
// kR: R = X @ inpt_mat   (NN gemm, M=512, N=512, K=512)
// ---------------------------------------------------------------------------
#define FMA16() \
    acc[0][0] += a.x*b.x; acc[0][1] += a.x*b.y; acc[0][2] += a.x*b.z; acc[0][3] += a.x*b.w; \
    acc[1][0] += a.y*b.x; acc[1][1] += a.y*b.y; acc[1][2] += a.y*b.z; acc[1][3] += a.y*b.w; \
    acc[2][0] += a.z*b.x; acc[2][1] += a.z*b.y; acc[2][2] += a.z*b.z; acc[2][3] += a.z*b.w; \
    acc[3][0] += a.w*b.x; acc[3][1] += a.w*b.y; acc[3][2] += a.w*b.z; acc[3][3] += a.w*b.w;

__global__ void kR(const float* __restrict__ X, const float* __restrict__ Bm)
{
    const int K = IDIM, N = IDIM;
    int mtile = blockIdx.x, ntile = blockIdx.y;
    int tid = threadIdx.x;
    __shared__ __align__(16) float As[32*36];
    __shared__ __align__(16) float Bs[32*68];
    float acc[4][4] = {};
    int tx = tid & 15, ty = tid >> 4;
    int m0 = ty*4, n0 = tx*4;
    for (int kb = 0; kb < K; kb += 32) {
        int k4 = tid & 7;
        int mrow = tid >> 3;
        #pragma unroll
        for (int r = 0; r < 2; r++) {
            int mm = mrow + r*16;
            float4 v = *(const float4*)(X + (mtile*32+mm)*K + kb + k4*4);
            As[(k4*4+0)*36+mm] = v.x;
            As[(k4*4+1)*36+mm] = v.y;
            As[(k4*4+2)*36+mm] = v.z;
            As[(k4*4+3)*36+mm] = v.w;
        }
        int n4 = tid & 15, kq = tid >> 4;
        #pragma unroll
        for (int r = 0; r < 4; r++) {
            int k = kq + r*8;
            float4 v = *(const float4*)(Bm + (kb+k)*N + ntile*64 + n4*4);
            *(float4*)&Bs[k*68 + n4*4] = v;
        }
        __syncthreads();
        #pragma unroll
        for (int kk = 0; kk < 32; kk++) {
            float4 a = *(const float4*)(As + kk*36 + m0);
            float4 b = *(const float4*)(Bs + kk*68 + n0);
            FMA16()
        }
        __syncthreads();
    }
    #pragma unroll
    for (int i = 0; i < 4; i++)
        *(float4*)&g_R[(mtile*32+m0+i)*N + ntile*64 + n0] =
            make_float4(acc[i][0], acc[i][1], acc[i][2], acc[i][3]);
}

// ---------------------------------------------------------------------------
// kYbase: ybase = X @ main_mat^T + bias  (NT gemm, M=512, N=1024, K=512)
// ---------------------------------------------------------------------------
__global__ void kYbase(const float* __restrict__ X, const float* __restrict__ W,
                       const float* __restrict__ bias)
{
    const int K = IDIM, N = HDIM;
    int ntile = blockIdx.x, mtile = blockIdx.y;
    int tid = threadIdx.x;
    __shared__ __align__(16) float As[32*68];
    __shared__ __align__(16) float Bs[32*68];
    float acc[4][4] = {};
    int tx = tid & 15, ty = tid >> 4;
    int m0 = ty*4, n0 = tx*4;
    for (int kb = 0; kb < K; kb += 32) {
        int k4 = tid & 7;
        int row = tid >> 3;
        #pragma unroll
        for (int r = 0; r < 2; r++) {
            int mm = row + r*32;
            float4 v = *(const float4*)(X + (mtile*64+mm)*K + kb + k4*4);
            As[(k4*4+0)*68+mm] = v.x;
            As[(k4*4+1)*68+mm] = v.y;
            As[(k4*4+2)*68+mm] = v.z;
            As[(k4*4+3)*68+mm] = v.w;
        }
        #pragma unroll
        for (int r = 0; r < 2; r++) {
            int nn = row + r*32;
            float4 v = *(const float4*)(W + (ntile*64+nn)*K + kb + k4*4);
            Bs[(k4*4+0)*68+nn] = v.x;
            Bs[(k4*4+1)*68+nn] = v.y;
            Bs[(k4*4+2)*68+nn] = v.z;
            Bs[(k4*4+3)*68+nn] = v.w;
        }
        __syncthreads();
        #pragma unroll
        for (int kk = 0; kk < 32; kk++) {
            float4 a = *(const float4*)(As + kk*68 + m0);
            float4 b = *(const float4*)(Bs + kk*68 + n0);
            FMA16()
        }
        __syncthreads();
    }
    #pragma unroll
    for (int i = 0; i < 4; i++) {
        int grow = mtile*64 + m0 + i;
        int col0 = ntile*64 + n0;
        float4 v = make_float4(acc[i][0] + bias[col0+0],
                               acc[i][1] + bias[col0+1],
                               acc[i][2] + bias[col0+2],
                               acc[i][3] + bias[col0+3]);
        *(float4*)&g_ybase[grow*N + col0] = v;
    }
}

// ---------------------------------------------------------------------------
// kD: D[t][s][b] = x_t[b] . R_s[b]  for s < t
// ---------------------------------------------------------------------------
__global__ void kD(const float* __restrict__ X)
{
    int t = blockIdx.x, s = blockIdx.y;
    if (s >= t) return;
    int w = threadIdx.x >> 5, lane = threadIdx.x & 31;
    for (int b = w; b < BB; b += 8) {
        const float* xb = X + (t*BB + b)*IDIM;
        const float* rb = g_R + (s*BB + b)*IDIM;
        float sum = 0.f;
        for (int i = lane; i < IDIM; i += 32) sum += xb[i]*rb[i];
        #pragma unroll
        for (int o = 16; o > 0; o >>= 1) sum += __shfl_down_sync(0xffffffffu, sum, o);
        if (lane == 0) g_D[(t*TT + s)*BB + b] = sum;
    }
}

// ---------------------------------------------------------------------------
// persistent kernel phases
// ---------------------------------------------------------------------------
// phase A: build A[32,1024] for GEMM (t,j). 1 elem/thread, no redundancy.
//   j=0: A = y_t   (reduce L_{t-1} partials, store g_L, history-combine)
//   j=1: A = relu(reduce + b1)
//   j=2: A = reduce + b2, also write out[t]
__device__ __forceinline__ void phaseA(int t, int j, const float* __restrict__ bias,
                                       float* __restrict__ out)
{
    int e = blockIdx.x * NTHR + threadIdx.x;   // 0..32767 == m*1024+col
    int m = e >> 10, col = e & 1023;
    float v;
    if (j == 0) {
        if (t == 0) {
            v = g_ybase[e];
        } else {
            const float* P = g_part[(3*t - 1) & 1];
            float lt = 0.f;
            #pragma unroll
            for (int kq = 0; kq < KS; kq++) lt += P[(kq*BB + m)*HDIM + col];
            g_L[((t-1)*BB + m)*HDIM + col] = lt;
            v = g_ybase[(t*BB + m)*HDIM + col];
            v += g_D[(t*TT + (t-1))*BB + m] * lt;          // s = t-1, d^0
            float dp = DECAYF;
            for (int s = t-2; s >= 0; s--) {
                v += dp * g_D[(t*TT + s)*BB + m] * g_L[(s*BB + m)*HDIM + col];
                dp *= DECAYF;
            }
        }
    } else {
        const float* P = g_part[(3*t + j - 1) & 1];
        float acc = bias[col];
        #pragma unroll
        for (int kq = 0; kq < KS; kq++) acc += P[(kq*BB + m)*HDIM + col];
        if (j == 1) v = fmaxf(acc, 0.f);
        else {
            v = acc;
            out[(t*BB + m)*HDIM + col] = v;
        }
    }
    g_A[e] = v;
}

// phase B: partials of A[32,1024] @ W[1024,1024]^T for this block's
// (ntile, ks) tile: 32m x 256n, K-slice 32.  8m x 4n microtile, FFMA2.
__device__ __forceinline__ void phaseB(const float* __restrict__ W, int g)
{
    int tid = threadIdx.x, blk = blockIdx.x;
    int ntile = blk & (NTILES-1);
    int ks = blk >> 2;
    int n_base = ntile*256, k_base = ks*32;
    __shared__ __align__(16) float As[32*36];     // [k][m]
    __shared__ __align__(16) float Bs[32*260];    // [k][n]

    // front-load global reads
    float4 bv[8];
    #pragma unroll
    for (int r = 0; r < 8; r++) {
        int idx = r*NTHR + tid;
        int row = idx >> 3, c = idx & 7;
        bv[r] = *(const float4*)(W + (n_base + row)*HDIM + k_base + c*4);
    }
    float av[4];
    #pragma unroll
    for (int r = 0; r < 4; r++) {
        int ea = r*NTHR + tid;
        av[r] = g_A[(ea >> 5)*HDIM + k_base + (ea & 31)];
    }
    #pragma unroll
    for (int r = 0; r < 8; r++) {
        int idx = r*NTHR + tid;
        int row = idx >> 3, c = idx & 7;
        Bs[(c*4+0)*260 + row] = bv[r].x;
        Bs[(c*4+1)*260 + row] = bv[r].y;
        Bs[(c*4+2)*260 + row] = bv[r].z;
        Bs[(c*4+3)*260 + row] = bv[r].w;
    }
    #pragma unroll
    for (int r = 0; r < 4; r++) {
        int ea = r*NTHR + tid;
        As[(ea & 31)*36 + (ea >> 5)] = av[r];
    }
    __syncthreads();

    int m0 = (tid >> 6) * 8;        // 4 m-groups of 8
    int n0 = (tid & 63) * 4;        // 64 n-groups of 4
    unsigned long long acc[4][4];
    #pragma unroll
    for (int i = 0; i < 4; i++)
        #pragma unroll
        for (int jj = 0; jj < 4; jj++) acc[i][jj] = 0ull;

    #pragma unroll
    for (int kk = 0; kk < 32; kk++) {
        union { float4 f; unsigned long long u[2]; } a0, a1;
        a0.f = *(const float4*)&As[kk*36 + m0];
        a1.f = *(const float4*)&As[kk*36 + m0 + 4];
        float4 b = *(const float4*)&Bs[kk*260 + n0];
        unsigned long long bp0 = rep2(b.x), bp1 = rep2(b.y),
                           bp2 = rep2(b.z), bp3 = rep2(b.w);
        ffma2(acc[0][0], a0.u[0], bp0); ffma2(acc[0][1], a0.u[0], bp1);
        ffma2(acc[0][2], a0.u[0], bp2); ffma2(acc[0][3], a0.u[0], bp3);
        ffma2(acc[1][0], a0.u[1], bp0); ffma2(acc[1][1], a0.u[1], bp1);
        ffma2(acc[1][2], a0.u[1], bp2); ffma2(acc[1][3], a0.u[1], bp3);
        ffma2(acc[2][0], a1.u[0], bp0); ffma2(acc[2][1], a1.u[0], bp1);
        ffma2(acc[2][2], a1.u[0], bp2); ffma2(acc[2][3], a1.u[0], bp3);
        ffma2(acc[3][0], a1.u[1], bp0); ffma2(acc[3][1], a1.u[1], bp1);
        ffma2(acc[3][2], a1.u[1], bp2); ffma2(acc[3][3], a1.u[1], bp3);
    }

    float* Pd = g_part[g & 1];
    #pragma unroll
    for (int mp = 0; mp < 4; mp++) {
        union { unsigned long long u; float2 f; } c0, c1, c2, c3;
        c0.u = acc[mp][0]; c1.u = acc[mp][1]; c2.u = acc[mp][2]; c3.u = acc[mp][3];
        int mrow = m0 + 2*mp;
        *(float4*)&Pd[(ks*BB + mrow    )*HDIM + n_base + n0] =
            make_float4(c0.f.x, c1.f.x, c2.f.x, c3.f.x);
        *(float4*)&Pd[(ks*BB + mrow + 1)*HDIM + n_base + n0] =
            make_float4(c0.f.y, c1.f.y, c2.f.y, c3.f.y);
    }
}

__global__ void __launch_bounds__(NTHR, 1)
stp_persist(const float* __restrict__ W1, const float* __restrict__ b1,
            const float* __restrict__ W2, const float* __restrict__ b2,
            const float* __restrict__ hidW, float* __restrict__ out)
{
    #pragma unroll 1
    for (int t = 0; t < TT; t++) {
        phaseA(t, 0, nullptr, nullptr); gridbar();
        phaseB(W1, 3*t + 0);            gridbar();
        phaseA(t, 1, b1, nullptr);      gridbar();
        phaseB(W2, 3*t + 1);            gridbar();
        phaseA(t, 2, b2, out);          gridbar();
        if (t < TT-1) { phaseB(hidW, 3*t + 2); gridbar(); }
    }
}

// ---------------------------------------------------------------------------
extern "C" void kernel_launch(void* const* d_in, const int* in_sizes, int n_in,
                              void* d_out, int out_size)
{
    (void)in_sizes; (void)n_in; (void)out_size;
    const float* x     = (const float*)d_in[0];
    const float* inpt  = (const float*)d_in[1];
    const float* hid   = (const float*)d_in[2];
    const float* mainW = (const float*)d_in[3];
    const float* mainb = (const float*)d_in[4];
    const float* W1    = (const float*)d_in[5];
    const float* b1    = (const float*)d_in[6];
    const float* W2    = (const float*)d_in[7];
    const float* b2    = (const float*)d_in[8];
    float* out = (float*)d_out;

    kR     <<<dim3(16, 8),  128>>>(x, inpt);
    kYbase <<<dim3(16, 8),  256>>>(x, mainW, mainb);
    kD     <<<dim3(16, 16), 256>>>(x);
    stp_persist<<<NBLK, NTHR>>>(W1, b1, W2, b2, hid, out);
}